// round 10
// baseline (speedup 1.0000x reference)
#include <cuda_runtime.h>
#include <cstdint>

// Problem constants (N=32768, D=64, K=64 per reference)
#define NPTS 32768
#define DIM 64
#define NK 64
#define ROWS_PER_BLOCK 64
#define NTHREADS 64
#define NBLOCKS (NPTS / ROWS_PER_BLOCK)   // 512

// Scratch (allocation-free rule: __device__ globals)
__device__ __align__(16) float d_negmuP[NK * DIM];  // -(means_k @ P_k), [K,D]
__device__ float d_Cpart[NK];                       // C without stick-breaking cumsum
__device__ float d_sdb[NK];                         // digamma(b)-digamma(a+b)

// ---------------------------------------------------------------------------
// NaN-proof helpers (identity on valid inputs).
// ---------------------------------------------------------------------------
static __device__ __forceinline__ double safe_log(double v) {
    v = fabs(v);
    if (v < 1e-300) v = 1e-300;
    return log(v);
}

// digamma in double. Recurrence terms computed as INDEPENDENT divides
// (mask-unrolled) — bit-identical values & summation order to the serial
// while-loop, but FP64-pipelinable. Valid for x >= 0.5 (our domain).
static __device__ __forceinline__ double digamma_d(double x) {
    if (!(x > 1e-6)) x = 1e-6;
    double r = 0.0;
    const double m = (x < 6.0) ? ceil(6.0 - x) : 0.0;   // <= 6 for x >= 0.5
#pragma unroll
    for (int j = 0; j < 6; ++j)
        if ((double)j < m) r -= 1.0 / (x + (double)j);
    x += m;
    const double inv  = 1.0 / x;
    const double inv2 = inv * inv;
    const double s = inv2 * (1.0 / 12.0
                   - inv2 * (1.0 / 120.0
                   - inv2 * (1.0 / 252.0
                   - inv2 * (1.0 / 240.0))));
    return r + log(x) - 0.5 * inv - s;
}

// ---------------------------------------------------------------------------
// Prep: 64 blocks (cluster k) x 64 threads (dimension i).
// Writes d_Cpart[k] (constant sans stick-breaking cumsum), d_sdb[k], negmuP.
// ---------------------------------------------------------------------------
__global__ void bgm_prep_a(const float* __restrict__ means,
                           const float* __restrict__ P,
                           const float* __restrict__ wc,
                           const float* __restrict__ v64a,
                           const float* __restrict__ v64b) {
    const int k = blockIdx.x;
    const int i = threadIdx.x;
    __shared__ double sd[NK];

    const bool a_is_dof = (v64a[0] > 32.0f);   // dof in [65,114], mp in (0.5,10]
    const float* __restrict__ dof = a_is_dof ? v64a : v64b;
    const float* __restrict__ mp  = a_is_dof ? v64b : v64a;

    const double dofk = (double)dof[k];

    const double t  = digamma_d(0.5 * (dofk - (double)i));
    const double lg = safe_log((double)P[k * DIM * DIM + i * DIM + i]);
    sd[i] = lg + 0.5 * t;
    __syncthreads();

    // negmuP column i
    {
        float s = 0.0f;
        for (int d = 0; d < DIM; ++d)
            s = fmaf(means[k * DIM + d], P[k * DIM * DIM + d * DIM + i], s);
        d_negmuP[k * DIM + i] = -s;
    }

    for (int off = 32; off > 0; off >>= 1) {
        if (i < off) sd[i] += sd[i + off];
        __syncthreads();
    }

    if (i == 0) {
        double mpk = (double)mp[k];
        if (!(mpk > 1e-6)) mpk = 1e-6;
        const double a  = (double)wc[k];
        const double b  = (double)wc[NK + k];
        const double ds = digamma_d(a + b);
        const double dga = digamma_d(a);
        const double dgb = digamma_d(b);
        double C = sd[0]
                 + 0.5 * (double)DIM * 0.69314718055994530942   // +0.5*D*log2
                 - 0.5 * (double)DIM * 1.8378770664093454836    // -0.5*D*log(2pi)
                 - 0.5 * (double)DIM * safe_log(dofk)
                 - 0.5 * (double)DIM / mpk
                 + dga - ds;
        d_Cpart[k] = (float)C;
        d_sdb[k]   = (float)(dgb - ds);
    }
}

// ---------------------------------------------------------------------------
// Packed f32x2 helpers (FFMA2 SASS — 2x scalar FFMA throughput on sm_103a)
// ---------------------------------------------------------------------------
static __device__ __forceinline__ unsigned long long ff2(
    unsigned long long a, unsigned long long b, unsigned long long c) {
    unsigned long long d;
    asm("fma.rn.f32x2 %0, %1, %2, %3;" : "=l"(d) : "l"(a), "l"(b), "l"(c));
    return d;
}
static __device__ __forceinline__ unsigned long long fadd2(
    unsigned long long a, unsigned long long b) {
    unsigned long long d;
    asm("add.rn.f32x2 %0, %1, %2;" : "=l"(d) : "l"(a), "l"(b));
    return d;
}
static __device__ __forceinline__ unsigned long long pack2(float x) {
    unsigned long long d;
    asm("mov.b64 %0, {%1, %1};" : "=l"(d) : "f"(x));
    return d;
}
static __device__ __forceinline__ void unpack2(unsigned long long v, float& lo, float& hi) {
    asm("mov.b64 {%0, %1}, %2;" : "=f"(lo), "=f"(hi) : "l"(v));
}

// cp.async 16B helpers
static __device__ __forceinline__ void cp16(uint32_t smem_addr, const void* gptr) {
    asm volatile("cp.async.cg.shared.global [%0], [%1], 16;" :: "r"(smem_addr), "l"(gptr));
}
static __device__ __forceinline__ void cp_commit() {
    asm volatile("cp.async.commit_group;");
}
template <int N>
static __device__ __forceinline__ void cp_wait() {
    asm volatile("cp.async.wait_group %0;" :: "n"(N));
}

// ---------------------------------------------------------------------------
// Main kernel: 512 blocks x 64 threads (2 warps). One thread = one X row.
// P_k upper-triangular: e-quarter q needs only d < 16(q+1) (bit-exact skip).
// Per quarter: 8 f32x2 accumulators. cp.async double-buffered P staging with
// block-wide barriers (2 warps share Psm). Stick-breaking cumsum computed
// in-block (bit-identical sequential order). OUTPUT: float32 index values.
// ---------------------------------------------------------------------------
__global__ __launch_bounds__(NTHREADS) void bgm_argmax_kernel(
    const float* __restrict__ X,
    const float* __restrict__ P,
    float* __restrict__ out) {

    __shared__ __align__(16) float Psm[2][DIM * DIM];                 // 2 x 16 KB
    __shared__ __align__(16) float Xsm[ROWS_PER_BLOCK * (DIM + 1)];   // padded
    __shared__ float Csm[NK];
    __shared__ float Sdb[NK];

    const int tid  = threadIdx.x;
    const int row0 = blockIdx.x * ROWS_PER_BLOCK;

    // Stage X tile: 64 rows -> 1024 float4, 16 per thread.
    {
        const float4* __restrict__ Xg =
            reinterpret_cast<const float4*>(X + row0 * DIM);
        for (int i = tid; i < ROWS_PER_BLOCK * (DIM / 4); i += NTHREADS) {
            const float4 v = Xg[i];
            const int r = i >> 4;
            const int c = (i & 15) << 2;
            float* dst = &Xsm[r * (DIM + 1) + c];
            dst[0] = v.x; dst[1] = v.y; dst[2] = v.z; dst[3] = v.w;
        }
    }
    Sdb[tid] = d_sdb[tid];           // NTHREADS == NK

    // Prologue: stage P_0 into buffer 0 (16 float4 per thread)
    {
        const float4* src = reinterpret_cast<const float4*>(P);
        const uint32_t dst = (uint32_t)__cvta_generic_to_shared(&Psm[0][0]);
#pragma unroll
        for (int j = 0; j < 16; ++j)
            cp16(dst + (tid + j * NTHREADS) * 16, src + tid + j * NTHREADS);
        cp_commit();
    }

    // Stick-breaking exclusive cumsum, bit-identical sequential fp32 order.
    __syncthreads();                 // Sdb visible
    {
        float pre = 0.0f;
        for (int j = 0; j < tid; ++j) pre += Sdb[j];
        Csm[tid] = d_Cpart[tid] + pre;
    }

    const int xb = tid * (DIM + 1);
    float best = __int_as_float(0xff800000u);   // -inf
    int   arg  = 0;

    const ulonglong2* __restrict__ nmAll =
        reinterpret_cast<const ulonglong2*>(d_negmuP);

    for (int k = 0; k < NK; ++k) {
        __syncthreads();   // both warps done reading buf[(k+1)&1] (holds P_{k-1});
                           // also covers Xsm/Csm staging at k=0
        if (k + 1 < NK) {
            const float4* src = reinterpret_cast<const float4*>(P + (k + 1) * DIM * DIM);
            const uint32_t dst =
                (uint32_t)__cvta_generic_to_shared(&Psm[(k + 1) & 1][0]);
#pragma unroll
            for (int j = 0; j < 16; ++j)
                cp16(dst + (tid + j * NTHREADS) * 16, src + tid + j * NTHREADS);
            cp_commit();
            cp_wait<1>();   // P_k ready (this warp's groups); P_{k+1} in flight
        } else {
            cp_wait<0>();
        }
        __syncthreads();    // P_k visible to both warps

        const float* __restrict__ Pk = Psm[k & 1];
        unsigned long long s0 = 0ULL;   // running sq as f32x2 pair

#pragma unroll
        for (int q = 0; q < 4; ++q) {   // e-quarter [16q, 16q+16)
            unsigned long long a0[8];
#pragma unroll
            for (int j = 0; j < 8; ++j) a0[j] = 0ULL;

            const int dmax = 16 * (q + 1);        // triangular bound
#pragma unroll 8
            for (int d = 0; d < dmax; ++d) {
                const unsigned long long x0 = pack2(Xsm[xb + d]);
                const ulonglong2* __restrict__ pr =
                    reinterpret_cast<const ulonglong2*>(Pk + (d << 6) + (q << 4));
#pragma unroll
                for (int j = 0; j < 4; ++j) {
                    const ulonglong2 p = pr[j];   // LDS.128 broadcast: 2 f32x2
                    a0[2 * j]     = ff2(x0, p.x, a0[2 * j]);
                    a0[2 * j + 1] = ff2(x0, p.y, a0[2 * j + 1]);
                }
            }

            // Quarter epilogue: s += (acc + negmuP_quarter)^2
            const ulonglong2* __restrict__ nm = nmAll + (k << 4) + (q << 2);
#pragma unroll
            for (int j = 0; j < 4; ++j) {
                const ulonglong2 m = nm[j];
                const unsigned long long e0a = fadd2(a0[2 * j],     m.x);
                const unsigned long long e0b = fadd2(a0[2 * j + 1], m.y);
                s0 = ff2(e0a, e0a, s0);
                s0 = ff2(e0b, e0b, s0);
            }
        }

        float lo, hi;
        unpack2(s0, lo, hi);
        const float sq = lo + hi;
        const float w  = fmaf(-0.5f, sq, Csm[k]);
        if (w > best) { best = w; arg = k; }   // strict >: first-max, like jnp.argmax
    }

    out[row0 + tid] = (float)arg;
}

// ---------------------------------------------------------------------------
// Launch. Inputs identified by ELEMENT COUNT; dof/mp disambiguated on device.
// Output: float32 index values [N].
// ---------------------------------------------------------------------------
extern "C" void kernel_launch(void* const* d_in, const int* in_sizes, int n_in,
                              void* d_out, int out_size) {
    (void)out_size;
    const float* X     = nullptr;
    const float* means = nullptr;
    const float* P     = nullptr;
    const float* wc    = nullptr;
    const float* v64a  = nullptr;
    const float* v64b  = nullptr;

    for (int i = 0; i < n_in; ++i) {
        const float* p = (const float*)d_in[i];
        switch (in_sizes[i]) {
            case 2097152: X = p; break;
            case 262144:  P = p; break;
            case 4096:    means = p; break;
            case 128:     wc = p; break;
            case 64:      if (!v64a) v64a = p; else v64b = p; break;
            default: break;
        }
    }
    if (!v64b) v64b = v64a;  // defensive
    float* out = (float*)d_out;

    bgm_prep_a<<<NK, DIM>>>(means, P, wc, v64a, v64b);
    bgm_argmax_kernel<<<NBLOCKS, NTHREADS>>>(X, P, out);
}